// round 7
// baseline (speedup 1.0000x reference)
#include <cuda_runtime.h>
#include <cstdint>

#define LN_EPS 1e-5f
#define H 768
#define F 11
#define RPB 64            // rows per block
#define TPB 192           // 192 threads x 4 cols = 768
#define CHUNK 8           // rows per bulk-store chunk (24KB)
#define NCHUNK (RPB / CHUNK)
#define ROWBYTES (H * 4)  // 3072

// [0..120] G[i*11+j], [121..131] ws, [132..142] Wb, [143] sum_b, [144] sum_b2
__device__ float g_stats[145];

typedef unsigned long long ull;

__device__ __forceinline__ ull fma2(ull a, ull b, ull c) {
    ull d; asm("fma.rn.f32x2 %0, %1, %2, %3;" : "=l"(d) : "l"(a), "l"(b), "l"(c)); return d;
}
__device__ __forceinline__ void unpk(ull v, float& lo, float& hi) {
    asm("mov.b64 {%0, %1}, %2;" : "=f"(lo), "=f"(hi) : "l"(v));
}
__device__ __forceinline__ uint32_t smem_u32(const void* p) {
    uint32_t a;
    asm("{ .reg .u64 t; cvta.to.shared.u64 t, %1; cvt.u32.u64 %0, t; }" : "=r"(a) : "l"(p));
    return a;
}

// ---------------------------------------------------------------------------
// Kernel A: weight statistics (145 tiny reductions over H=768)
// ---------------------------------------------------------------------------
__global__ void stats_kernel(const float* __restrict__ W, const float* __restrict__ b) {
    __shared__ float wsum[8];
    int blk = blockIdx.x, tid = threadIdx.x;
    float local = 0.f;
    if (blk < 121) {
        int i = blk / 11, j = blk % 11;
        for (int h = tid; h < H; h += 256) local += W[i * H + h] * W[j * H + h];
    } else if (blk < 132) {
        int f = blk - 121;
        for (int h = tid; h < H; h += 256) local += W[f * H + h];
    } else if (blk < 143) {
        int f = blk - 132;
        for (int h = tid; h < H; h += 256) local += W[f * H + h] * b[h];
    } else if (blk == 143) {
        for (int h = tid; h < H; h += 256) local += b[h];
    } else {
        for (int h = tid; h < H; h += 256) local += b[h] * b[h];
    }
    #pragma unroll
    for (int o = 16; o; o >>= 1) local += __shfl_xor_sync(0xffffffffu, local, o);
    if ((tid & 31) == 0) wsum[tid >> 5] = local;
    __syncthreads();
    if (tid == 0) {
        float s = 0.f;
        #pragma unroll
        for (int w = 0; w < 8; w++) s += wsum[w];
        g_stats[blk] = s;
    }
}

// ---------------------------------------------------------------------------
// Kernel B (fused): per-block feats -> smem (duplicated pairs),
// packed-FFMA2 GEMV+LN+ReLU into double-buffered smem tiles, TMA bulk stores.
// ---------------------------------------------------------------------------
__global__ void __launch_bounds__(TPB, 3)
fused_kernel(const float* __restrict__ target, const float* __restrict__ boxes,
             const float* __restrict__ W, const float* __restrict__ b,
             const float* __restrict__ gamma, const float* __restrict__ beta,
             float* __restrict__ out, int N) {
    __shared__ __align__(128) float obuf[2][CHUNK * H];   // 2 x 24KB
    __shared__ __align__(16)  float fst[RPB][32];         // 13 duplicated pairs + pad
    __shared__ float st[148];

    int tid = threadIdx.x;
    int h0 = tid * 4;

    for (int i = tid; i < 145; i += TPB) st[i] = g_stats[i];

    // resident slices: Wg = W*gamma, bg = b*gamma, plus gamma/beta (packed pairs)
    ull gp[2], ep[2], bg[2];
    float g4[4];
    {
        float4 g = *(const float4*)(gamma + h0);
        float4 e = *(const float4*)(beta + h0);
        float4 bb = *(const float4*)(b + h0);
        g4[0] = g.x; g4[1] = g.y; g4[2] = g.z; g4[3] = g.w;
        asm("mov.b64 %0, {%1, %2};" : "=l"(gp[0]) : "f"(g.x), "f"(g.y));
        asm("mov.b64 %0, {%1, %2};" : "=l"(gp[1]) : "f"(g.z), "f"(g.w));
        asm("mov.b64 %0, {%1, %2};" : "=l"(ep[0]) : "f"(e.x), "f"(e.y));
        asm("mov.b64 %0, {%1, %2};" : "=l"(ep[1]) : "f"(e.z), "f"(e.w));
        float b0 = bb.x * g.x, b1 = bb.y * g.y, b2 = bb.z * g.z, b3 = bb.w * g.w;
        asm("mov.b64 %0, {%1, %2};" : "=l"(bg[0]) : "f"(b0), "f"(b1));
        asm("mov.b64 %0, {%1, %2};" : "=l"(bg[1]) : "f"(b2), "f"(b3));
    }
    ull wg[F][2];
    #pragma unroll
    for (int f = 0; f < F; f++) {
        float4 wv = *(const float4*)(W + f * H + h0);
        float w0 = wv.x * g4[0], w1 = wv.y * g4[1];
        float w2 = wv.z * g4[2], w3 = wv.w * g4[3];
        asm("mov.b64 %0, {%1, %2};" : "=l"(wg[f][0]) : "f"(w0), "f"(w1));
        asm("mov.b64 %0, {%1, %2};" : "=l"(wg[f][1]) : "f"(w2), "f"(w3));
    }

    int r0blk = blockIdx.x * RPB;
    __syncthreads();   // st[] ready

    // ---- feats phase: one row per thread (tid < 64) ----
    if (tid < RPB) {
        int row = r0blk + tid;
        if (row < N) {
            float tx0 = target[0], ty0 = target[1], tx1 = target[2], ty1 = target[3];
            float4 bx = ((const float4*)boxes)[row];
            float x0 = bx.x, y0 = bx.y, x1 = bx.z, y1 = bx.w;

            float w1 = tx1 - tx0, h1 = ty1 - ty0;
            float w2 = x1 - x0,   h2 = y1 - y0;

            float t[F];
            t[0] = w1; t[1] = h1; t[2] = w2; t[3] = h2;
            t[4] = fabsf(w1 - w2); t[5] = fabsf(h1 - h2);

            float c1x = (tx0 + tx1) * 0.5f, c1y = (ty0 + ty1) * 0.5f;
            float c2x = (x0 + x1) * 0.5f,   c2y = (y0 + y1) * 0.5f;
            float dx = c2x - c1x, dy = c2y - c1y;
            t[6] = sqrtf(dx * dx + dy * dy);

            bool overlap = (tx0 < x1) && (tx1 > x0) && (ty0 < y1) && (ty1 > y0);
            float xi0 = fmaxf(tx0, x0), yi0 = fmaxf(ty0, y0);
            float xi1 = fminf(tx1, x1), yi1 = fminf(ty1, y1);
            float inter = overlap ? (xi1 - xi0) * (yi1 - yi0) : 0.f;
            float a1 = w1 * h1, a2 = w2 * h2;
            float uni = a1 + a2 - inter;
            t[7] = inter / uni; t[8] = inter / a1; t[9] = inter / a2;

            float degree = atan2f(fabsf(dy), fabsf(dx)) * 57.29577951308232f;
            float bucket;
            if      (degree >  22.5f && degree <=  67.5f) bucket = 1.f;
            else if (degree >  67.5f && degree <= 112.5f) bucket = 2.f;
            else if (degree > 112.5f && degree <= 157.5f) bucket = 3.f;
            else if (degree > 157.5f && degree <= 202.5f) bucket = 4.f;
            else if (degree > 202.5f && degree <= 247.5f) bucket = 5.f;
            else if (degree > 247.5f && degree <= 292.5f) bucket = 6.f;
            else if (degree > 292.5f && degree <= 337.5f) bucket = 7.f;
            else bucket = 8.f;
            t[10] = bucket;

            // closed-form LN stats
            const float* G  = st;
            const float* ws = st + 121;
            const float* Wb = st + 132;
            float S1 = st[143];
            float S2 = st[144];
            #pragma unroll
            for (int i = 0; i < F; i++) {
                S1 += t[i] * ws[i];
                S2 += 2.f * t[i] * Wb[i];
                float gi = 0.f;
                #pragma unroll
                for (int j = 0; j < F; j++) gi += G[i * 11 + j] * t[j];
                S2 += t[i] * gi;
            }
            float mean = S1 * (1.f / (float)H);
            float var  = S2 * (1.f / (float)H) - mean * mean;
            float inv  = rsqrtf(var + LN_EPS);

            float2* fp = (float2*)fst[tid];
            #pragma unroll
            for (int i = 0; i < F; i++) {
                float u = t[i] * inv;
                fp[i] = make_float2(u, u);
            }
            fp[11] = make_float2(inv, inv);               // s
            float p = -mean * inv;
            fp[12] = make_float2(p, p);                   // p
            fp[13] = make_float2(0.f, 0.f);
        }
    }
    __syncthreads();

    // ---- chunk loop: compute into smem, bulk-store to global ----
    for (int c = 0; c < NCHUNK; ++c) {
        int cr0 = r0blk + c * CHUNK;
        if (cr0 >= N) break;
        int nrows = min(CHUNK, N - cr0);
        float* buf = obuf[c & 1];

        if (c >= 2) {
            if (tid == 0)
                asm volatile("cp.async.bulk.wait_group 1;" ::: "memory");
            __syncthreads();
        }

        for (int i = 0; i < nrows; ++i) {
            const ulonglong2* fq = (const ulonglong2*)fst[c * CHUNK + i];
            ulonglong2 q0 = fq[0], q1 = fq[1], q2 = fq[2], q3 = fq[3];
            ulonglong2 q4 = fq[4], q5 = fq[5], q6 = fq[6];
            ull u[F] = {q0.x, q0.y, q1.x, q1.y, q2.x, q2.y,
                        q3.x, q3.y, q4.x, q4.y, q5.x};
            ull s2 = q5.y;   // (inv, inv)
            ull p2 = q6.x;   // (-mean*inv, ..)

            ull acc0 = fma2(p2, gp[0], ep[0]);
            ull acc1 = fma2(p2, gp[1], ep[1]);
            acc0 = fma2(s2, bg[0], acc0);
            acc1 = fma2(s2, bg[1], acc1);
            #pragma unroll
            for (int f = 0; f < F; f++) {
                acc0 = fma2(u[f], wg[f][0], acc0);
                acc1 = fma2(u[f], wg[f][1], acc1);
            }

            float v0, v1, v2, v3;
            unpk(acc0, v0, v1);
            unpk(acc1, v2, v3);
            float4 o;
            o.x = fmaxf(v0, 0.f); o.y = fmaxf(v1, 0.f);
            o.z = fmaxf(v2, 0.f); o.w = fmaxf(v3, 0.f);
            *(float4*)(buf + i * H + h0) = o;
        }

        asm volatile("fence.proxy.async.shared::cta;" ::: "memory");
        __syncthreads();

        if (tid == 0) {
            uint32_t saddr = smem_u32(buf);
            const void* gptr = (const void*)(out + (size_t)cr0 * H);
            uint32_t bytes = (uint32_t)nrows * ROWBYTES;
            asm volatile(
                "cp.async.bulk.global.shared::cta.bulk_group [%0], [%1], %2;"
                :: "l"(gptr), "r"(saddr), "r"(bytes) : "memory");
            asm volatile("cp.async.bulk.commit_group;" ::: "memory");
        }
    }

    if (tid == 0)
        asm volatile("cp.async.bulk.wait_group 0;" ::: "memory");
}

// ---------------------------------------------------------------------------
extern "C" void kernel_launch(void* const* d_in, const int* in_sizes, int n_in,
                              void* d_out, int out_size) {
    if (n_in < 6) return;
    const float* target = (const float*)d_in[0];
    const float* boxes  = (const float*)d_in[1];
    const float* W      = (const float*)d_in[2];
    const float* b      = (const float*)d_in[3];
    const float* gamma  = (const float*)d_in[4];
    const float* beta   = (const float*)d_in[5];
    float* out = (float*)d_out;

    int N = in_sizes[1] / 4;

    stats_kernel<<<145, 256>>>(W, b);
    fused_kernel<<<(N + RPB - 1) / RPB, TPB>>>(target, boxes, W, b, gamma, beta, out, N);
}